// round 6
// baseline (speedup 1.0000x reference)
#include <cuda_runtime.h>
#include <cuda_bf16.h>
#include <cstdint>

#define T_LEN 16384
#define DIM   1024
#define NCHUNK 256
#define CLEN   64

// ---------------- scratch (static device globals; no allocation) ----------------
__device__ __align__(16) float  g_gain[DIM];
__device__ float2 g_lam[DIM];
__device__ float2 g_lamL[DIM];
__device__ float2 g_carry [NCHUNK * DIM];
__device__ float2 g_carry2[NCHUNK * DIM];

// bf16 operands (all K-major: [row][k], k contiguous)
__device__ __align__(16) __nv_bfloat16 g_x_hi  [(size_t)T_LEN * DIM];
__device__ __align__(16) __nv_bfloat16 g_x_lo  [(size_t)T_LEN * DIM];
__device__ __align__(16) __nv_bfloat16 g_bure16[(size_t)T_LEN * DIM];  // Bu re (bf16)
__device__ __align__(16) __nv_bfloat16 g_buim16[(size_t)T_LEN * DIM];  // Bu im (bf16)
__device__ __align__(16) __nv_bfloat16 g_hre_hi[(size_t)T_LEN * DIM];  // hidden re
__device__ __align__(16) __nv_bfloat16 g_him_hi[(size_t)T_LEN * DIM];  // hidden im
__device__ __align__(16) __nv_bfloat16 g_brt_hi[DIM * DIM];   // (B_re*gain)^T  [h][i]
__device__ __align__(16) __nv_bfloat16 g_bit_hi[DIM * DIM];   // (B_im*gain)^T  [h][i]
__device__ __align__(16) __nv_bfloat16 g_cre_hi[DIM * DIM];   // C_re           [o][h]
__device__ __align__(16) __nv_bfloat16 g_cin_hi[DIM * DIM];   // -C_im          [o][h]
__device__ __align__(16) __nv_bfloat16 g_dt_hi [DIM * DIM];   // D^T            [o][i]
__device__ __align__(16) __nv_bfloat16 g_dt_lo [DIM * DIM];

// ---------------- PTX helpers ----------------
__device__ __forceinline__ unsigned smem_u32(const void* p) {
    unsigned a;
    asm("{ .reg .u64 t; cvta.to.shared.u64 t, %1; cvt.u32.u64 %0, t; }" : "=r"(a) : "l"(p));
    return a;
}
__device__ __forceinline__ void ldsm4(uint32_t* r, unsigned a) {
    asm volatile("ldmatrix.sync.aligned.m8n8.x4.shared.b16 {%0,%1,%2,%3}, [%4];"
        : "=r"(r[0]), "=r"(r[1]), "=r"(r[2]), "=r"(r[3]) : "r"(a));
}
__device__ __forceinline__ void mma16816(float* c, const uint32_t* a, uint32_t b0, uint32_t b1) {
    asm volatile(
        "mma.sync.aligned.m16n8k16.row.col.f32.bf16.bf16.f32 "
        "{%0,%1,%2,%3}, {%4,%5,%6,%7}, {%8,%9}, {%0,%1,%2,%3};"
        : "+f"(c[0]), "+f"(c[1]), "+f"(c[2]), "+f"(c[3])
        : "r"(a[0]), "r"(a[1]), "r"(a[2]), "r"(a[3]), "r"(b0), "r"(b1));
}
__device__ __forceinline__ void cp16(unsigned dst, const void* src) {
    asm volatile("cp.async.cg.shared.global [%0], [%1], 16;" :: "r"(dst), "l"(src) : "memory");
}
#define CP_COMMIT() asm volatile("cp.async.commit_group;" ::: "memory")
#define CP_WAIT2()  asm volatile("cp.async.wait_group 2;" ::: "memory")

// ---------------- setup ----------------
__global__ void setup_kernel(const float* __restrict__ nu_log,
                             const float* __restrict__ theta_log,
                             const float* __restrict__ gamma_log) {
    int h = blockIdx.x * blockDim.x + threadIdx.x;
    if (h >= DIM) return;
    float nu = expf(nu_log[h]);
    float th = expf(theta_log[h]);
    float r  = expf(-nu);
    float lr = r * cosf(th);
    float li = r * sinf(th);
    g_lam[h] = make_float2(lr, li);
    float ar = lr, ai = li;
#pragma unroll
    for (int s = 0; s < 6; s++) {
        float nr = ar * ar - ai * ai;
        float ni = 2.0f * ar * ai;
        ar = nr; ai = ni;
    }
    g_lamL[h] = make_float2(ar, ai);
    g_gain[h] = expf(gamma_log[h]);
}

// ---------------- prep: elementwise split ----------------
// mode 0: X -> hi+lo, 1: Cre -> hi, 2: -Cim -> hi
__global__ __launch_bounds__(256) void split_mat(const float* __restrict__ src, int mode, int n) {
    int i = (blockIdx.x * blockDim.x + threadIdx.x) * 4;
    if (i >= n) return;
    float4 v = *(const float4*)(src + i);
    float sign = (mode == 2) ? -1.0f : 1.0f;
    float vv[4] = {v.x * sign, v.y * sign, v.z * sign, v.w * sign};
    __nv_bfloat16 h4[4], l4[4];
#pragma unroll
    for (int j = 0; j < 4; j++) {
        __nv_bfloat16 h = __float2bfloat16(vv[j]);
        h4[j] = h;
        l4[j] = __float2bfloat16(vv[j] - __bfloat162float(h));
    }
    __nv_bfloat16* hi = (mode == 0) ? g_x_hi : (mode == 1 ? g_cre_hi : g_cin_hi);
    *(uint2*)(hi + i) = *(uint2*)h4;
    if (mode == 0) *(uint2*)(g_x_lo + i) = *(uint2*)l4;
}

// ---------------- prep: transpose + split (gain-scaled B_re/B_im; D hi+lo) ----------------
__global__ void transpose_split(const float* __restrict__ src, int mode) {
    __shared__ float tl[32][33];
    int bx = blockIdx.x * 32, by = blockIdx.y * 32;
    int tx = threadIdx.x, ty = threadIdx.y;
    bool use_gain = (mode != 2);
#pragma unroll
    for (int r = 0; r < 4; r++) {
        int row = by + ty + r * 8;
        float v = src[(size_t)row * DIM + bx + tx];
        if (use_gain) v *= g_gain[row];
        tl[ty + r * 8][tx] = v;
    }
    __syncthreads();
    __nv_bfloat16* hi = (mode == 0) ? g_brt_hi : (mode == 1 ? g_bit_hi : g_dt_hi);
#pragma unroll
    for (int r = 0; r < 4; r++) {
        float v = tl[tx][ty + r * 8];
        __nv_bfloat16 h = __float2bfloat16(v);
        size_t o = (size_t)(bx + ty + r * 8) * DIM + by + tx;
        hi[o] = h;
        if (mode == 2) g_dt_lo[o] = __float2bfloat16(v - __bfloat162float(h));
    }
}

// ================= GEMM1 fused: Bu_re/Bu_im = X_hi @ {Brt, Bit}^T =================
// BM=128, BN=64, BK=64, 256 threads (2x4 warps), 4-stage cp.async ring.
// Stage: A 16KB @0, Br 8KB @16384, Bi 8KB @24576; stride 32768; total 128KB.
__global__ __launch_bounds__(256) void gemm1_mma() {
    extern __shared__ __align__(128) char sm[];
    unsigned sbase = smem_u32(sm);
    const int tid = threadIdx.x, lane = tid & 31, w = tid >> 5;
    const int wm = w & 1, wn = w >> 1;          // wm: 2x64 rows, wn: 4x16 cols
    const int n0 = blockIdx.x * 64, m0 = blockIdx.y * 128;
    const int NK = 16;

    float cr[4][2][4], ci[4][2][4];
#pragma unroll
    for (int a = 0; a < 4; a++)
#pragma unroll
        for (int b = 0; b < 2; b++)
#pragma unroll
            for (int d = 0; d < 4; d++) { cr[a][b][d] = 0.f; ci[a][b][d] = 0.f; }

    auto load_stage = [&](int stage, int kt) {
        unsigned sb = sbase + stage * 32768;
        int k0 = kt * 64;
#pragma unroll
        for (int i = 0; i < 4; i++) {
            int idx = tid + i * 256; int row = idx >> 3, g = idx & 7;
            unsigned sw = (unsigned)(row * 128 + ((g ^ (row & 7)) << 4));
            cp16(sb + sw, g_x_hi + (size_t)(m0 + row) * DIM + k0 + g * 8);
        }
#pragma unroll
        for (int i = 0; i < 2; i++) {
            int idx = tid + i * 256; int row = idx >> 3, g = idx & 7;
            unsigned sw = (unsigned)(row * 128 + ((g ^ (row & 7)) << 4));
            cp16(sb + 16384 + sw, g_brt_hi + (size_t)(n0 + row) * DIM + k0 + g * 8);
            cp16(sb + 24576 + sw, g_bit_hi + (size_t)(n0 + row) * DIM + k0 + g * 8);
        }
    };

    load_stage(0, 0); CP_COMMIT();
    load_stage(1, 1); CP_COMMIT();
    load_stage(2, 2); CP_COMMIT();

    const int lr = lane & 15, lh = lane >> 4;
    for (int kt = 0; kt < NK; kt++) {
        CP_WAIT2();
        __syncthreads();
        if (kt + 3 < NK) load_stage((kt + 3) & 3, kt + 3);
        CP_COMMIT();
        unsigned sb = sbase + (kt & 3) * 32768;
#pragma unroll
        for (int ks = 0; ks < 4; ks++) {
            uint32_t a[4][4];
#pragma unroll
            for (int mf = 0; mf < 4; mf++) {
                int row = wm * 64 + mf * 16 + lr;
                int kg = ks * 2 + lh;
                ldsm4(a[mf], sb + row * 128 + ((kg ^ (row & 7)) << 4));
            }
            uint32_t br[4], bi[4];
            {
                int row = wn * 16 + lr;
                int kg = ks * 2 + lh;
                ldsm4(br, sb + 16384 + row * 128 + ((kg ^ (row & 7)) << 4));
                ldsm4(bi, sb + 24576 + row * 128 + ((kg ^ (row & 7)) << 4));
            }
#pragma unroll
            for (int mf = 0; mf < 4; mf++) {
                mma16816(cr[mf][0], a[mf], br[0], br[2]);
                mma16816(cr[mf][1], a[mf], br[1], br[3]);
                mma16816(ci[mf][0], a[mf], bi[0], bi[2]);
                mma16816(ci[mf][1], a[mf], bi[1], bi[3]);
            }
        }
        __syncthreads();
    }

#pragma unroll
    for (int mf = 0; mf < 4; mf++) {
#pragma unroll
        for (int nf = 0; nf < 2; nf++) {
            int r   = wm * 64 + mf * 16 + (lane >> 2);
            int col = wn * 16 + nf * 8  + (lane & 3) * 2;
            size_t o = (size_t)(m0 + r) * DIM + n0 + col;
            *(__nv_bfloat162*)(g_bure16 + o) = __floats2bfloat162_rn(cr[mf][nf][0], cr[mf][nf][1]);
            *(__nv_bfloat162*)(g_bure16 + o + 8 * DIM) = __floats2bfloat162_rn(cr[mf][nf][2], cr[mf][nf][3]);
            *(__nv_bfloat162*)(g_buim16 + o) = __floats2bfloat162_rn(ci[mf][nf][0], ci[mf][nf][1]);
            *(__nv_bfloat162*)(g_buim16 + o + 8 * DIM) = __floats2bfloat162_rn(ci[mf][nf][2], ci[mf][nf][3]);
        }
    }
}

// ================= GEMM2: out = Hr@Cre^T + Hi@(-Cim)^T + X@D =================
// BM=BN=128, BK=64, 5 register-accumulated passes, 4-stage ring (A16KB+B16KB)/stage.
__device__ __forceinline__ void pass2_ptrs(int kt, const __nv_bfloat16*& A,
                                           const __nv_bfloat16*& B, int& k0) {
    int p = kt >> 4; k0 = (kt & 15) * 64;
    switch (p) {
        case 0:  A = g_hre_hi; B = g_cre_hi; break;
        case 1:  A = g_him_hi; B = g_cin_hi; break;
        case 2:  A = g_x_hi;   B = g_dt_hi;  break;
        case 3:  A = g_x_hi;   B = g_dt_lo;  break;
        default: A = g_x_lo;   B = g_dt_hi;  break;
    }
}

__global__ __launch_bounds__(256) void gemm2_mma(float* __restrict__ outp) {
    extern __shared__ __align__(128) char sm[];
    unsigned sbase = smem_u32(sm);
    const int tid = threadIdx.x, lane = tid & 31, w = tid >> 5;
    const int wm = w & 1, wn = w >> 1;
    const int n0 = blockIdx.x * 128, m0 = blockIdx.y * 128;
    const int NK = 80;

    float c[4][4][4];
#pragma unroll
    for (int a = 0; a < 4; a++)
#pragma unroll
        for (int b = 0; b < 4; b++)
#pragma unroll
            for (int d = 0; d < 4; d++) c[a][b][d] = 0.f;

    auto load_stage = [&](int stage, int kt) {
        const __nv_bfloat16 *A, *B; int k0;
        pass2_ptrs(kt, A, B, k0);
        unsigned sb = sbase + stage * 32768;
#pragma unroll
        for (int i = 0; i < 4; i++) {
            int idx = tid + i * 256; int row = idx >> 3, g = idx & 7;
            unsigned sw = (unsigned)(row * 128 + ((g ^ (row & 7)) << 4));
            cp16(sb + sw, A + (size_t)(m0 + row) * DIM + k0 + g * 8);
            cp16(sb + 16384 + sw, B + (size_t)(n0 + row) * DIM + k0 + g * 8);
        }
    };

    load_stage(0, 0); CP_COMMIT();
    load_stage(1, 1); CP_COMMIT();
    load_stage(2, 2); CP_COMMIT();

    const int lr = lane & 15, lh = lane >> 4;
    for (int kt = 0; kt < NK; kt++) {
        CP_WAIT2();
        __syncthreads();
        if (kt + 3 < NK) load_stage((kt + 3) & 3, kt + 3);
        CP_COMMIT();
        unsigned sA = sbase + (kt & 3) * 32768;
        unsigned sB = sA + 16384;
#pragma unroll
        for (int ks = 0; ks < 4; ks++) {
            uint32_t a[4][4];
#pragma unroll
            for (int mf = 0; mf < 4; mf++) {
                int row = wm * 64 + mf * 16 + lr;
                int kg = ks * 2 + lh;
                ldsm4(a[mf], sA + row * 128 + ((kg ^ (row & 7)) << 4));
            }
            uint32_t bb[2][4];
#pragma unroll
            for (int nh = 0; nh < 2; nh++) {
                int row = wn * 32 + nh * 16 + lr;
                int kg = ks * 2 + lh;
                ldsm4(bb[nh], sB + row * 128 + ((kg ^ (row & 7)) << 4));
            }
#pragma unroll
            for (int mf = 0; mf < 4; mf++) {
                mma16816(c[mf][0], a[mf], bb[0][0], bb[0][2]);
                mma16816(c[mf][1], a[mf], bb[0][1], bb[0][3]);
                mma16816(c[mf][2], a[mf], bb[1][0], bb[1][2]);
                mma16816(c[mf][3], a[mf], bb[1][1], bb[1][3]);
            }
        }
        __syncthreads();
    }

#pragma unroll
    for (int mf = 0; mf < 4; mf++) {
#pragma unroll
        for (int nf = 0; nf < 4; nf++) {
            int r   = wm * 64 + mf * 16 + (lane >> 2);
            int col = wn * 32 + nf * 8  + (lane & 3) * 2;
            size_t o = (size_t)(m0 + r) * DIM + n0 + col;
            *(float2*)(outp + o) = make_float2(c[mf][nf][0], c[mf][nf][1]);
            *(float2*)(outp + o + 8 * DIM) = make_float2(c[mf][nf][2], c[mf][nf][3]);
        }
    }
}

// ---------------- scan pass 1: chunk carries only (read-only on Bu) ----------------
__global__ __launch_bounds__(256) void scan_carry() {
    int h = blockIdx.y * blockDim.x + threadIdx.x;
    int c = blockIdx.x;
    float2 lam = g_lam[h];
    float ar = 0.f, ai = 0.f;
    size_t idx = (size_t)c * CLEN * DIM + h;
#pragma unroll 4
    for (int t = 0; t < CLEN; t++, idx += DIM) {
        float br = __bfloat162float(g_bure16[idx]);
        float bi = __bfloat162float(g_buim16[idx]);
        float nr = fmaf(lam.x, ar, fmaf(-lam.y, ai, br));
        float ni = fmaf(lam.x, ai, fmaf( lam.y, ar, bi));
        ar = nr; ai = ni;
    }
    g_carry[c * DIM + h] = make_float2(ar, ai);
}

// ---------------- scan pass 2: prefix over chunk carries ----------------
__global__ __launch_bounds__(256) void scan_chunks() {
    int h = blockIdx.x * blockDim.x + threadIdx.x;
    float2 lamL = g_lamL[h];
    float pr = 0.f, pi = 0.f;
#pragma unroll 4
    for (int c = 0; c < NCHUNK; c++) {
        float2 e = g_carry[c * DIM + h];
        float nr = fmaf(lamL.x, pr, fmaf(-lamL.y, pi, e.x));
        float ni = fmaf(lamL.x, pi, fmaf( lamL.y, pr, e.y));
        pr = nr; pi = ni;
        g_carry2[c * DIM + h] = make_float2(pr, pi);
    }
}

// ---------------- scan pass 3: rerun recurrence with carry-in, write bf16 H ----------------
__global__ __launch_bounds__(256) void scan_apply_all() {
    int h = blockIdx.y * blockDim.x + threadIdx.x;
    int c = blockIdx.x;
    float2 P = (c == 0) ? make_float2(0.f, 0.f) : g_carry2[(c - 1) * DIM + h];
    float2 lam = g_lam[h];
    float ar = P.x, ai = P.y;
    size_t idx = (size_t)c * CLEN * DIM + h;
#pragma unroll 4
    for (int t = 0; t < CLEN; t++, idx += DIM) {
        float br = __bfloat162float(g_bure16[idx]);
        float bi = __bfloat162float(g_buim16[idx]);
        float nr = fmaf(lam.x, ar, fmaf(-lam.y, ai, br));
        float ni = fmaf(lam.x, ai, fmaf( lam.y, ar, bi));
        ar = nr; ai = ni;
        g_hre_hi[idx] = __float2bfloat16(ar);
        g_him_hi[idx] = __float2bfloat16(ai);
    }
}

// ---------------- launch ----------------
extern "C" void kernel_launch(void* const* d_in, const int* in_sizes, int n_in,
                              void* d_out, int out_size) {
    const float* X         = (const float*)d_in[0];
    const float* nu_log    = (const float*)d_in[1];
    const float* theta_log = (const float*)d_in[2];
    const float* gamma_log = (const float*)d_in[3];
    const float* Bre       = (const float*)d_in[4];
    const float* Bim       = (const float*)d_in[5];
    const float* Cre       = (const float*)d_in[6];
    const float* Cim       = (const float*)d_in[7];
    const float* Dm        = (const float*)d_in[8];
    float* out             = (float*)d_out;

    cudaFuncSetAttribute(gemm1_mma, cudaFuncAttributeMaxDynamicSharedMemorySize, 131072);
    cudaFuncSetAttribute(gemm2_mma, cudaFuncAttributeMaxDynamicSharedMemorySize, 131072);

    setup_kernel<<<4, 256>>>(nu_log, theta_log, gamma_log);
    split_mat<<<T_LEN * DIM / 4 / 256, 256>>>(X, 0, T_LEN * DIM);
    split_mat<<<DIM * DIM / 4 / 256, 256>>>(Cre, 1, DIM * DIM);
    split_mat<<<DIM * DIM / 4 / 256, 256>>>(Cim, 2, DIM * DIM);
    transpose_split<<<dim3(32, 32), dim3(32, 8)>>>(Bre, 0);
    transpose_split<<<dim3(32, 32), dim3(32, 8)>>>(Bim, 1);
    transpose_split<<<dim3(32, 32), dim3(32, 8)>>>(Dm, 2);

    gemm1_mma<<<dim3(DIM / 64, T_LEN / 128), 256, 131072>>>();

    scan_carry<<<dim3(NCHUNK, DIM / 256), 256>>>();
    scan_chunks<<<DIM / 256, 256>>>();
    scan_apply_all<<<dim3(NCHUNK, DIM / 256), 256>>>();

    gemm2_mma<<<dim3(DIM / 128, T_LEN / 128), 256, 131072>>>(out);
}

// round 7
// speedup vs baseline: 1.2072x; 1.2072x over previous
#include <cuda_runtime.h>
#include <cuda_bf16.h>
#include <cstdint>

#define T_LEN 16384
#define DIM   1024
#define NCHUNK 256
#define CLEN   64

// ---------------- scratch (static device globals; no allocation) ----------------
__device__ __align__(16) float  g_gain[DIM];
__device__ float2 g_lam[DIM];
__device__ float2 g_lamL[DIM];
__device__ float2 g_carry [NCHUNK * DIM];
__device__ float2 g_carry2[NCHUNK * DIM];

// bf16 operands (all K-major: [row][k], k contiguous)
__device__ __align__(16) __nv_bfloat16 g_x_hi  [(size_t)T_LEN * DIM];
__device__ __align__(16) __nv_bfloat16 g_x_lo  [(size_t)T_LEN * DIM];
__device__ __align__(16) __nv_bfloat16 g_bure16[(size_t)T_LEN * DIM];
__device__ __align__(16) __nv_bfloat16 g_buim16[(size_t)T_LEN * DIM];
__device__ __align__(16) __nv_bfloat16 g_hre_hi[(size_t)T_LEN * DIM];
__device__ __align__(16) __nv_bfloat16 g_him_hi[(size_t)T_LEN * DIM];
__device__ __align__(16) __nv_bfloat16 g_brt_hi[DIM * DIM];   // (B_re*gain)^T [h][i]
__device__ __align__(16) __nv_bfloat16 g_bit_hi[DIM * DIM];   // (B_im*gain)^T [h][i]
__device__ __align__(16) __nv_bfloat16 g_cre_hi[DIM * DIM];   // C_re          [o][h]
__device__ __align__(16) __nv_bfloat16 g_cin_hi[DIM * DIM];   // -C_im         [o][h]
__device__ __align__(16) __nv_bfloat16 g_dt_hi [DIM * DIM];   // D^T           [o][i]
__device__ __align__(16) __nv_bfloat16 g_dt_lo [DIM * DIM];

// ---------------- PTX helpers ----------------
__device__ __forceinline__ unsigned smem_u32(const void* p) {
    unsigned a;
    asm("{ .reg .u64 t; cvta.to.shared.u64 t, %1; cvt.u32.u64 %0, t; }" : "=r"(a) : "l"(p));
    return a;
}
__device__ __forceinline__ void ldsm4(uint32_t* r, unsigned a) {
    asm volatile("ldmatrix.sync.aligned.m8n8.x4.shared.b16 {%0,%1,%2,%3}, [%4];"
        : "=r"(r[0]), "=r"(r[1]), "=r"(r[2]), "=r"(r[3]) : "r"(a));
}
__device__ __forceinline__ void mma16816(float* c, const uint32_t* a, uint32_t b0, uint32_t b1) {
    asm volatile(
        "mma.sync.aligned.m16n8k16.row.col.f32.bf16.bf16.f32 "
        "{%0,%1,%2,%3}, {%4,%5,%6,%7}, {%8,%9}, {%0,%1,%2,%3};"
        : "+f"(c[0]), "+f"(c[1]), "+f"(c[2]), "+f"(c[3])
        : "r"(a[0]), "r"(a[1]), "r"(a[2]), "r"(a[3]), "r"(b0), "r"(b1));
}
__device__ __forceinline__ void cp16(unsigned dst, const void* src) {
    asm volatile("cp.async.cg.shared.global [%0], [%1], 16;" :: "r"(dst), "l"(src) : "memory");
}
#define CP_COMMIT() asm volatile("cp.async.commit_group;" ::: "memory")
#define CP_WAIT1()  asm volatile("cp.async.wait_group 1;" ::: "memory")

// ---------------- setup ----------------
__global__ void setup_kernel(const float* __restrict__ nu_log,
                             const float* __restrict__ theta_log,
                             const float* __restrict__ gamma_log) {
    int h = blockIdx.x * blockDim.x + threadIdx.x;
    if (h >= DIM) return;
    float nu = expf(nu_log[h]);
    float th = expf(theta_log[h]);
    float r  = expf(-nu);
    float lr = r * cosf(th);
    float li = r * sinf(th);
    g_lam[h] = make_float2(lr, li);
    float ar = lr, ai = li;
#pragma unroll
    for (int s = 0; s < 6; s++) {
        float nr = ar * ar - ai * ai;
        float ni = 2.0f * ar * ai;
        ar = nr; ai = ni;
    }
    g_lamL[h] = make_float2(ar, ai);
    g_gain[h] = expf(gamma_log[h]);
}

// ---------------- prep: elementwise split ----------------
// mode 0: X -> hi+lo, 1: Cre -> hi, 2: -Cim -> hi
__global__ __launch_bounds__(256) void split_mat(const float* __restrict__ src, int mode, int n) {
    int i = (blockIdx.x * blockDim.x + threadIdx.x) * 4;
    if (i >= n) return;
    float4 v = *(const float4*)(src + i);
    float sign = (mode == 2) ? -1.0f : 1.0f;
    float vv[4] = {v.x * sign, v.y * sign, v.z * sign, v.w * sign};
    __nv_bfloat16 h4[4], l4[4];
#pragma unroll
    for (int j = 0; j < 4; j++) {
        __nv_bfloat16 h = __float2bfloat16(vv[j]);
        h4[j] = h;
        l4[j] = __float2bfloat16(vv[j] - __bfloat162float(h));
    }
    __nv_bfloat16* hi = (mode == 0) ? g_x_hi : (mode == 1 ? g_cre_hi : g_cin_hi);
    *(uint2*)(hi + i) = *(uint2*)h4;
    if (mode == 0) *(uint2*)(g_x_lo + i) = *(uint2*)l4;
}

// ---------------- prep: transpose + split (gain-scaled B_re/B_im; D hi+lo) ----------------
__global__ void transpose_split(const float* __restrict__ src, int mode) {
    __shared__ float tl[32][33];
    int bx = blockIdx.x * 32, by = blockIdx.y * 32;
    int tx = threadIdx.x, ty = threadIdx.y;
    bool use_gain = (mode != 2);
#pragma unroll
    for (int r = 0; r < 4; r++) {
        int row = by + ty + r * 8;
        float v = src[(size_t)row * DIM + bx + tx];
        if (use_gain) v *= g_gain[row];
        tl[ty + r * 8][tx] = v;
    }
    __syncthreads();
    __nv_bfloat16* hi = (mode == 0) ? g_brt_hi : (mode == 1 ? g_bit_hi : g_dt_hi);
#pragma unroll
    for (int r = 0; r < 4; r++) {
        float v = tl[tx][ty + r * 8];
        __nv_bfloat16 h = __float2bfloat16(v);
        size_t o = (size_t)(bx + ty + r * 8) * DIM + by + tx;
        hi[o] = h;
        if (mode == 2) g_dt_lo[o] = __float2bfloat16(v - __bfloat162float(h));
    }
}

// ================= generic TN bf16 GEMM, BM=BN=128, BK=64, 3-stage ring =================
// smem: 3 stages x (A 16KB + B 16KB) = 96KB  -> 2 CTAs/SM.

__device__ __forceinline__ void pass_ptrs(int mode, int z, int kt,
        const __nv_bfloat16*& A, const __nv_bfloat16*& B, int& k0) {
    if (mode == 0) {
        A = g_x_hi; B = z ? g_bit_hi : g_brt_hi; k0 = kt * 64;
    } else {
        int p = kt >> 4; k0 = (kt & 15) * 64;
        switch (p) {
            case 0:  A = g_hre_hi; B = g_cre_hi; break;
            case 1:  A = g_him_hi; B = g_cin_hi; break;
            case 2:  A = g_x_hi;   B = g_dt_hi;  break;
            case 3:  A = g_x_hi;   B = g_dt_lo;  break;
            default: A = g_x_lo;   B = g_dt_hi;  break;
        }
    }
}

__global__ __launch_bounds__(256) void gemm_mma(int mode, float* __restrict__ outp) {
    extern __shared__ __align__(128) char sm[];
    unsigned sbase = smem_u32(sm);
    const int tid = threadIdx.x, lane = tid & 31, w = tid >> 5;
    const int wm = w & 1, wn = w >> 1;
    const int n0 = blockIdx.x * 128, m0 = blockIdx.y * 128;
    const int z  = blockIdx.z;
    const int NK = (mode == 0) ? 16 : 80;

    float c[4][4][4];
#pragma unroll
    for (int a = 0; a < 4; a++)
#pragma unroll
        for (int b = 0; b < 4; b++)
#pragma unroll
            for (int d = 0; d < 4; d++) c[a][b][d] = 0.f;

    auto load_stage = [&](int stage, int kt) {
        const __nv_bfloat16 *A, *B; int k0;
        pass_ptrs(mode, z, kt, A, B, k0);
        unsigned sb = sbase + stage * 32768;
#pragma unroll
        for (int i = 0; i < 4; i++) {
            int idx = tid + i * 256; int row = idx >> 3, g = idx & 7;
            unsigned sw = (unsigned)(row * 128 + ((g ^ (row & 7)) << 4));
            cp16(sb + sw, A + (size_t)(m0 + row) * DIM + k0 + g * 8);
            cp16(sb + 16384 + sw, B + (size_t)(n0 + row) * DIM + k0 + g * 8);
        }
    };

    load_stage(0, 0); CP_COMMIT();
    load_stage(1, 1); CP_COMMIT();

    const int lr = lane & 15, lh = lane >> 4;
    int st = 0;                         // stage holding tile kt
    for (int kt = 0; kt < NK; kt++) {
        CP_WAIT1();
        __syncthreads();
        // issue next load into the free stage BEFORE compute
        if (kt + 2 < NK) {
            int free_st = st + 2; if (free_st >= 3) free_st -= 3;
            load_stage(free_st, kt + 2);
        }
        CP_COMMIT();
        unsigned sA = sbase + st * 32768;
        unsigned sB = sA + 16384;
#pragma unroll
        for (int ks = 0; ks < 4; ks++) {
            uint32_t a[4][4];
#pragma unroll
            for (int mf = 0; mf < 4; mf++) {
                int row = wm * 64 + mf * 16 + lr;
                int kg = ks * 2 + lh;
                ldsm4(a[mf], sA + row * 128 + ((kg ^ (row & 7)) << 4));
            }
            uint32_t bb[2][4];
#pragma unroll
            for (int nh = 0; nh < 2; nh++) {
                int row = wn * 32 + nh * 16 + lr;
                int kg = ks * 2 + lh;
                ldsm4(bb[nh], sB + row * 128 + ((kg ^ (row & 7)) << 4));
            }
#pragma unroll
            for (int mf = 0; mf < 4; mf++) {
                mma16816(c[mf][0], a[mf], bb[0][0], bb[0][2]);
                mma16816(c[mf][1], a[mf], bb[0][1], bb[0][3]);
                mma16816(c[mf][2], a[mf], bb[1][0], bb[1][2]);
                mma16816(c[mf][3], a[mf], bb[1][1], bb[1][3]);
            }
        }
        st++; if (st >= 3) st = 0;
    }

    if (mode == 0) {
        __nv_bfloat16* dst = z ? g_buim16 : g_bure16;
#pragma unroll
        for (int mf = 0; mf < 4; mf++) {
#pragma unroll
            for (int nf = 0; nf < 4; nf++) {
                int r   = wm * 64 + mf * 16 + (lane >> 2);
                int col = wn * 32 + nf * 8  + (lane & 3) * 2;
                size_t o = (size_t)(m0 + r) * DIM + n0 + col;
                *(__nv_bfloat162*)(dst + o) = __floats2bfloat162_rn(c[mf][nf][0], c[mf][nf][1]);
                *(__nv_bfloat162*)(dst + o + 8 * DIM) = __floats2bfloat162_rn(c[mf][nf][2], c[mf][nf][3]);
            }
        }
    } else {
#pragma unroll
        for (int mf = 0; mf < 4; mf++) {
#pragma unroll
            for (int nf = 0; nf < 4; nf++) {
                int r   = wm * 64 + mf * 16 + (lane >> 2);
                int col = wn * 32 + nf * 8  + (lane & 3) * 2;
                size_t o = (size_t)(m0 + r) * DIM + n0 + col;
                *(float2*)(outp + o) = make_float2(c[mf][nf][0], c[mf][nf][1]);
                *(float2*)(outp + o + 8 * DIM) = make_float2(c[mf][nf][2], c[mf][nf][3]);
            }
        }
    }
}

// ---------------- scan pass 1: chunk carries only (read-only on Bu) ----------------
__global__ __launch_bounds__(256) void scan_carry() {
    int h = blockIdx.y * blockDim.x + threadIdx.x;
    int c = blockIdx.x;
    float2 lam = g_lam[h];
    float ar = 0.f, ai = 0.f;
    size_t idx = (size_t)c * CLEN * DIM + h;
#pragma unroll 4
    for (int t = 0; t < CLEN; t++, idx += DIM) {
        float br = __bfloat162float(g_bure16[idx]);
        float bi = __bfloat162float(g_buim16[idx]);
        float nr = fmaf(lam.x, ar, fmaf(-lam.y, ai, br));
        float ni = fmaf(lam.x, ai, fmaf( lam.y, ar, bi));
        ar = nr; ai = ni;
    }
    g_carry[c * DIM + h] = make_float2(ar, ai);
}

// ---------------- scan pass 2: prefix over chunk carries ----------------
__global__ __launch_bounds__(256) void scan_chunks() {
    int h = blockIdx.x * blockDim.x + threadIdx.x;
    float2 lamL = g_lamL[h];
    float pr = 0.f, pi = 0.f;
#pragma unroll 4
    for (int c = 0; c < NCHUNK; c++) {
        float2 e = g_carry[c * DIM + h];
        float nr = fmaf(lamL.x, pr, fmaf(-lamL.y, pi, e.x));
        float ni = fmaf(lamL.x, pi, fmaf( lamL.y, pr, e.y));
        pr = nr; pi = ni;
        g_carry2[c * DIM + h] = make_float2(pr, pi);
    }
}

// ---------------- scan pass 3: rerun recurrence with carry-in, write bf16 H ----------------
__global__ __launch_bounds__(256) void scan_apply_all() {
    int h = blockIdx.y * blockDim.x + threadIdx.x;
    int c = blockIdx.x;
    float2 P = (c == 0) ? make_float2(0.f, 0.f) : g_carry2[(c - 1) * DIM + h];
    float2 lam = g_lam[h];
    float ar = P.x, ai = P.y;
    size_t idx = (size_t)c * CLEN * DIM + h;
#pragma unroll 4
    for (int t = 0; t < CLEN; t++, idx += DIM) {
        float br = __bfloat162float(g_bure16[idx]);
        float bi = __bfloat162float(g_buim16[idx]);
        float nr = fmaf(lam.x, ar, fmaf(-lam.y, ai, br));
        float ni = fmaf(lam.x, ai, fmaf( lam.y, ar, bi));
        ar = nr; ai = ni;
        g_hre_hi[idx] = __float2bfloat16(ar);
        g_him_hi[idx] = __float2bfloat16(ai);
    }
}

// ---------------- launch ----------------
extern "C" void kernel_launch(void* const* d_in, const int* in_sizes, int n_in,
                              void* d_out, int out_size) {
    const float* X         = (const float*)d_in[0];
    const float* nu_log    = (const float*)d_in[1];
    const float* theta_log = (const float*)d_in[2];
    const float* gamma_log = (const float*)d_in[3];
    const float* Bre       = (const float*)d_in[4];
    const float* Bim       = (const float*)d_in[5];
    const float* Cre       = (const float*)d_in[6];
    const float* Cim       = (const float*)d_in[7];
    const float* Dm        = (const float*)d_in[8];
    float* out             = (float*)d_out;

    cudaFuncSetAttribute(gemm_mma, cudaFuncAttributeMaxDynamicSharedMemorySize, 98304);

    setup_kernel<<<4, 256>>>(nu_log, theta_log, gamma_log);
    split_mat<<<T_LEN * DIM / 4 / 256, 256>>>(X, 0, T_LEN * DIM);
    split_mat<<<DIM * DIM / 4 / 256, 256>>>(Cre, 1, DIM * DIM);
    split_mat<<<DIM * DIM / 4 / 256, 256>>>(Cim, 2, DIM * DIM);
    transpose_split<<<dim3(32, 32), dim3(32, 8)>>>(Bre, 0);
    transpose_split<<<dim3(32, 32), dim3(32, 8)>>>(Bim, 1);
    transpose_split<<<dim3(32, 32), dim3(32, 8)>>>(Dm, 2);

    // GEMM1: Bu_re / Bu_im via blockIdx.z, bf16 output
    gemm_mma<<<dim3(DIM / 128, T_LEN / 128, 2), 256, 98304>>>(0, nullptr);

    scan_carry<<<dim3(NCHUNK, DIM / 256), 256>>>();
    scan_chunks<<<DIM / 256, 256>>>();
    scan_apply_all<<<dim3(NCHUNK, DIM / 256), 256>>>();

    // GEMM2: out = Hr@Cre^T + Hi@(-Cim)^T + X@D (5 register-accumulated passes)
    gemm_mma<<<dim3(DIM / 128, T_LEN / 128, 1), 256, 98304>>>(1, out);
}

// round 8
// speedup vs baseline: 1.2802x; 1.0605x over previous
#include <cuda_runtime.h>
#include <cuda_bf16.h>
#include <cstdint>

#define T_LEN 16384
#define DIM   1024
#define NCHUNK 256
#define CLEN   64

// ---------------- scratch (static device globals; no allocation) ----------------
__device__ __align__(16) float  g_gain[DIM];
__device__ float2 g_lam[DIM];
__device__ float2 g_lamL[DIM];
__device__ float2 g_carry [NCHUNK * DIM];
__device__ float2 g_carry2[NCHUNK * DIM];

// bf16 operands (all K-major: [row][k], k contiguous)
__device__ __align__(16) __nv_bfloat16 g_x_hi  [(size_t)T_LEN * DIM];
__device__ __align__(16) __nv_bfloat16 g_x_lo  [(size_t)T_LEN * DIM];
__device__ __align__(16) __nv_bfloat16 g_bure16[(size_t)T_LEN * DIM];
__device__ __align__(16) __nv_bfloat16 g_buim16[(size_t)T_LEN * DIM];
__device__ __align__(16) __nv_bfloat16 g_hre_hi[(size_t)T_LEN * DIM];
__device__ __align__(16) __nv_bfloat16 g_him_hi[(size_t)T_LEN * DIM];
__device__ __align__(16) __nv_bfloat16 g_brt_hi[DIM * DIM];   // (B_re*gain)^T [h][i]
__device__ __align__(16) __nv_bfloat16 g_bit_hi[DIM * DIM];   // (B_im*gain)^T [h][i]
__device__ __align__(16) __nv_bfloat16 g_cre_hi[DIM * DIM];   // C_re          [o][h]
__device__ __align__(16) __nv_bfloat16 g_cin_hi[DIM * DIM];   // -C_im         [o][h]
__device__ __align__(16) __nv_bfloat16 g_dt_hi [DIM * DIM];   // D^T           [o][i]
__device__ __align__(16) __nv_bfloat16 g_dt_lo [DIM * DIM];

// ---------------- PTX helpers ----------------
__device__ __forceinline__ unsigned smem_u32(const void* p) {
    unsigned a;
    asm("{ .reg .u64 t; cvta.to.shared.u64 t, %1; cvt.u32.u64 %0, t; }" : "=r"(a) : "l"(p));
    return a;
}
__device__ __forceinline__ void ldsm4(uint32_t* r, unsigned a) {
    asm volatile("ldmatrix.sync.aligned.m8n8.x4.shared.b16 {%0,%1,%2,%3}, [%4];"
        : "=r"(r[0]), "=r"(r[1]), "=r"(r[2]), "=r"(r[3]) : "r"(a));
}
__device__ __forceinline__ void mma16816(float* c, const uint32_t* a, uint32_t b0, uint32_t b1) {
    asm volatile(
        "mma.sync.aligned.m16n8k16.row.col.f32.bf16.bf16.f32 "
        "{%0,%1,%2,%3}, {%4,%5,%6,%7}, {%8,%9}, {%0,%1,%2,%3};"
        : "+f"(c[0]), "+f"(c[1]), "+f"(c[2]), "+f"(c[3])
        : "r"(a[0]), "r"(a[1]), "r"(a[2]), "r"(a[3]), "r"(b0), "r"(b1));
}
__device__ __forceinline__ void cp16(unsigned dst, const void* src) {
    asm volatile("cp.async.cg.shared.global [%0], [%1], 16;" :: "r"(dst), "l"(src) : "memory");
}
#define CP_COMMIT() asm volatile("cp.async.commit_group;" ::: "memory")
#define CP_WAIT1()  asm volatile("cp.async.wait_group 1;" ::: "memory")

// ---------------- setup ----------------
__global__ void setup_kernel(const float* __restrict__ nu_log,
                             const float* __restrict__ theta_log,
                             const float* __restrict__ gamma_log) {
    int h = blockIdx.x * blockDim.x + threadIdx.x;
    if (h >= DIM) return;
    float nu = expf(nu_log[h]);
    float th = expf(theta_log[h]);
    float r  = expf(-nu);
    float lr = r * cosf(th);
    float li = r * sinf(th);
    g_lam[h] = make_float2(lr, li);
    float ar = lr, ai = li;
#pragma unroll
    for (int s = 0; s < 6; s++) {
        float nr = ar * ar - ai * ai;
        float ni = 2.0f * ar * ai;
        ar = nr; ai = ni;
    }
    g_lamL[h] = make_float2(ar, ai);
    g_gain[h] = expf(gamma_log[h]);
}

// ---------------- prep: elementwise split ----------------
// mode 0: X -> hi+lo, 1: Cre -> hi, 2: -Cim -> hi
__global__ __launch_bounds__(256) void split_mat(const float* __restrict__ src, int mode, int n) {
    int i = (blockIdx.x * blockDim.x + threadIdx.x) * 4;
    if (i >= n) return;
    float4 v = *(const float4*)(src + i);
    float sign = (mode == 2) ? -1.0f : 1.0f;
    float vv[4] = {v.x * sign, v.y * sign, v.z * sign, v.w * sign};
    __nv_bfloat16 h4[4], l4[4];
#pragma unroll
    for (int j = 0; j < 4; j++) {
        __nv_bfloat16 h = __float2bfloat16(vv[j]);
        h4[j] = h;
        l4[j] = __float2bfloat16(vv[j] - __bfloat162float(h));
    }
    __nv_bfloat16* hi = (mode == 0) ? g_x_hi : (mode == 1 ? g_cre_hi : g_cin_hi);
    *(uint2*)(hi + i) = *(uint2*)h4;
    if (mode == 0) *(uint2*)(g_x_lo + i) = *(uint2*)l4;
}

// ---------------- prep: transpose + split (gain-scaled B_re/B_im; D hi+lo) ----------------
__global__ void transpose_split(const float* __restrict__ src, int mode) {
    __shared__ float tl[32][33];
    int bx = blockIdx.x * 32, by = blockIdx.y * 32;
    int tx = threadIdx.x, ty = threadIdx.y;
    bool use_gain = (mode != 2);
#pragma unroll
    for (int r = 0; r < 4; r++) {
        int row = by + ty + r * 8;
        float v = src[(size_t)row * DIM + bx + tx];
        if (use_gain) v *= g_gain[row];
        tl[ty + r * 8][tx] = v;
    }
    __syncthreads();
    __nv_bfloat16* hi = (mode == 0) ? g_brt_hi : (mode == 1 ? g_bit_hi : g_dt_hi);
#pragma unroll
    for (int r = 0; r < 4; r++) {
        float v = tl[tx][ty + r * 8];
        __nv_bfloat16 h = __float2bfloat16(v);
        size_t o = (size_t)(bx + ty + r * 8) * DIM + by + tx;
        hi[o] = h;
        if (mode == 2) g_dt_lo[o] = __float2bfloat16(v - __bfloat162float(h));
    }
}

// ================= generic TN bf16 GEMM, BM=BN=128, BK=64, 3-stage ring =================
// smem: 3 x (A 16KB + B 16KB) = 96KB; regs capped for 2 CTAs/SM.

__device__ __forceinline__ void pass_ptrs(int mode, int z, int kt,
        const __nv_bfloat16*& A, const __nv_bfloat16*& B, int& k0) {
    if (mode == 0) {
        A = g_x_hi; B = z ? g_bit_hi : g_brt_hi; k0 = kt * 64;
    } else {
        int p = kt >> 4; k0 = (kt & 15) * 64;
        switch (p) {
            case 0:  A = g_hre_hi; B = g_cre_hi; break;
            case 1:  A = g_him_hi; B = g_cin_hi; break;
            case 2:  A = g_x_hi;   B = g_dt_hi;  break;
            case 3:  A = g_x_hi;   B = g_dt_lo;  break;
            default: A = g_x_lo;   B = g_dt_hi;  break;
        }
    }
}

__global__ __launch_bounds__(256, 2) void gemm_mma(int mode, float* __restrict__ outp) {
    extern __shared__ __align__(128) char sm[];
    unsigned sbase = smem_u32(sm);
    const int tid = threadIdx.x, lane = tid & 31, w = tid >> 5;
    const int wm = w & 1, wn = w >> 1;
    const int n0 = blockIdx.x * 128, m0 = blockIdx.y * 128;
    const int z  = blockIdx.z;
    const int NK = (mode == 0) ? 16 : 80;

    float c[4][4][4];
#pragma unroll
    for (int a = 0; a < 4; a++)
#pragma unroll
        for (int b = 0; b < 4; b++)
#pragma unroll
            for (int d = 0; d < 4; d++) c[a][b][d] = 0.f;

    auto load_stage = [&](int stage, int kt) {
        const __nv_bfloat16 *A, *B; int k0;
        pass_ptrs(mode, z, kt, A, B, k0);
        unsigned sb = sbase + stage * 32768;
#pragma unroll
        for (int i = 0; i < 4; i++) {
            int idx = tid + i * 256; int row = idx >> 3, g = idx & 7;
            unsigned sw = (unsigned)(row * 128 + ((g ^ (row & 7)) << 4));
            cp16(sb + sw, A + (size_t)(m0 + row) * DIM + k0 + g * 8);
            cp16(sb + 16384 + sw, B + (size_t)(n0 + row) * DIM + k0 + g * 8);
        }
    };

    load_stage(0, 0); CP_COMMIT();
    load_stage(1, 1); CP_COMMIT();

    const int lr = lane & 15, lh = lane >> 4;
    int st = 0;                         // stage holding tile kt
    for (int kt = 0; kt < NK; kt++) {
        CP_WAIT1();
        __syncthreads();
        // issue next load into the free stage BEFORE compute
        if (kt + 2 < NK) {
            int free_st = st + 2; if (free_st >= 3) free_st -= 3;
            load_stage(free_st, kt + 2);
        }
        CP_COMMIT();
        unsigned sA = sbase + st * 32768;
        unsigned sB = sA + 16384;
#pragma unroll
        for (int ks = 0; ks < 4; ks++) {
            int kg = ks * 2 + lh;
            uint32_t bb[2][4];
#pragma unroll
            for (int nh = 0; nh < 2; nh++) {
                int row = wn * 32 + nh * 16 + lr;
                ldsm4(bb[nh], sB + row * 128 + ((kg ^ (row & 7)) << 4));
            }
            // one A fragment live at a time (register pressure: 2 CTAs/SM)
#pragma unroll
            for (int mf = 0; mf < 4; mf++) {
                uint32_t a[4];
                int row = wm * 64 + mf * 16 + lr;
                ldsm4(a, sA + row * 128 + ((kg ^ (row & 7)) << 4));
                mma16816(c[mf][0], a, bb[0][0], bb[0][2]);
                mma16816(c[mf][1], a, bb[0][1], bb[0][3]);
                mma16816(c[mf][2], a, bb[1][0], bb[1][2]);
                mma16816(c[mf][3], a, bb[1][1], bb[1][3]);
            }
        }
        st++; if (st >= 3) st = 0;
    }

    if (mode == 0) {
        __nv_bfloat16* dst = z ? g_buim16 : g_bure16;
#pragma unroll
        for (int mf = 0; mf < 4; mf++) {
#pragma unroll
            for (int nf = 0; nf < 4; nf++) {
                int r   = wm * 64 + mf * 16 + (lane >> 2);
                int col = wn * 32 + nf * 8  + (lane & 3) * 2;
                size_t o = (size_t)(m0 + r) * DIM + n0 + col;
                *(__nv_bfloat162*)(dst + o) = __floats2bfloat162_rn(c[mf][nf][0], c[mf][nf][1]);
                *(__nv_bfloat162*)(dst + o + 8 * DIM) = __floats2bfloat162_rn(c[mf][nf][2], c[mf][nf][3]);
            }
        }
    } else {
#pragma unroll
        for (int mf = 0; mf < 4; mf++) {
#pragma unroll
            for (int nf = 0; nf < 4; nf++) {
                int r   = wm * 64 + mf * 16 + (lane >> 2);
                int col = wn * 32 + nf * 8  + (lane & 3) * 2;
                size_t o = (size_t)(m0 + r) * DIM + n0 + col;
                *(float2*)(outp + o) = make_float2(c[mf][nf][0], c[mf][nf][1]);
                *(float2*)(outp + o + 8 * DIM) = make_float2(c[mf][nf][2], c[mf][nf][3]);
            }
        }
    }
}

// ---------------- scan pass 1: chunk carries only (read-only on Bu) ----------------
__global__ __launch_bounds__(256) void scan_carry() {
    int h = blockIdx.y * blockDim.x + threadIdx.x;
    int c = blockIdx.x;
    float2 lam = g_lam[h];
    float ar = 0.f, ai = 0.f;
    size_t idx = (size_t)c * CLEN * DIM + h;
#pragma unroll 4
    for (int t = 0; t < CLEN; t++, idx += DIM) {
        float br = __bfloat162float(g_bure16[idx]);
        float bi = __bfloat162float(g_buim16[idx]);
        float nr = fmaf(lam.x, ar, fmaf(-lam.y, ai, br));
        float ni = fmaf(lam.x, ai, fmaf( lam.y, ar, bi));
        ar = nr; ai = ni;
    }
    g_carry[c * DIM + h] = make_float2(ar, ai);
}

// ---------------- scan pass 2: prefix over chunk carries (batched loads for MLP) ----------------
__global__ __launch_bounds__(256) void scan_chunks() {
    int h = blockIdx.x * blockDim.x + threadIdx.x;
    float2 lamL = g_lamL[h];
    float pr = 0.f, pi = 0.f;
    for (int cb = 0; cb < NCHUNK; cb += 32) {
        float2 e[32];
#pragma unroll
        for (int j = 0; j < 32; j++) e[j] = g_carry[(cb + j) * DIM + h];
#pragma unroll
        for (int j = 0; j < 32; j++) {
            float nr = fmaf(lamL.x, pr, fmaf(-lamL.y, pi, e[j].x));
            float ni = fmaf(lamL.x, pi, fmaf( lamL.y, pr, e[j].y));
            pr = nr; pi = ni;
            e[j] = make_float2(pr, pi);
        }
#pragma unroll
        for (int j = 0; j < 32; j++) g_carry2[(cb + j) * DIM + h] = e[j];
    }
}

// ---------------- scan pass 3: rerun recurrence with carry-in, write bf16 H ----------------
__global__ __launch_bounds__(256) void scan_apply_all() {
    int h = blockIdx.y * blockDim.x + threadIdx.x;
    int c = blockIdx.x;
    float2 P = (c == 0) ? make_float2(0.f, 0.f) : g_carry2[(c - 1) * DIM + h];
    float2 lam = g_lam[h];
    float ar = P.x, ai = P.y;
    size_t idx = (size_t)c * CLEN * DIM + h;
#pragma unroll 4
    for (int t = 0; t < CLEN; t++, idx += DIM) {
        float br = __bfloat162float(g_bure16[idx]);
        float bi = __bfloat162float(g_buim16[idx]);
        float nr = fmaf(lam.x, ar, fmaf(-lam.y, ai, br));
        float ni = fmaf(lam.x, ai, fmaf( lam.y, ar, bi));
        ar = nr; ai = ni;
        g_hre_hi[idx] = __float2bfloat16(ar);
        g_him_hi[idx] = __float2bfloat16(ai);
    }
}

// ---------------- launch ----------------
extern "C" void kernel_launch(void* const* d_in, const int* in_sizes, int n_in,
                              void* d_out, int out_size) {
    const float* X         = (const float*)d_in[0];
    const float* nu_log    = (const float*)d_in[1];
    const float* theta_log = (const float*)d_in[2];
    const float* gamma_log = (const float*)d_in[3];
    const float* Bre       = (const float*)d_in[4];
    const float* Bim       = (const float*)d_in[5];
    const float* Cre       = (const float*)d_in[6];
    const float* Cim       = (const float*)d_in[7];
    const float* Dm        = (const float*)d_in[8];
    float* out             = (float*)d_out;

    cudaFuncSetAttribute(gemm_mma, cudaFuncAttributeMaxDynamicSharedMemorySize, 98304);

    setup_kernel<<<4, 256>>>(nu_log, theta_log, gamma_log);
    split_mat<<<T_LEN * DIM / 4 / 256, 256>>>(X, 0, T_LEN * DIM);
    split_mat<<<DIM * DIM / 4 / 256, 256>>>(Cre, 1, DIM * DIM);
    split_mat<<<DIM * DIM / 4 / 256, 256>>>(Cim, 2, DIM * DIM);
    transpose_split<<<dim3(32, 32), dim3(32, 8)>>>(Bre, 0);
    transpose_split<<<dim3(32, 32), dim3(32, 8)>>>(Bim, 1);
    transpose_split<<<dim3(32, 32), dim3(32, 8)>>>(Dm, 2);

    // GEMM1: Bu_re / Bu_im via blockIdx.z, bf16 output
    gemm_mma<<<dim3(DIM / 128, T_LEN / 128, 2), 256, 98304>>>(0, nullptr);

    scan_carry<<<dim3(NCHUNK, DIM / 256), 256>>>();
    scan_chunks<<<DIM / 256, 256>>>();
    scan_apply_all<<<dim3(NCHUNK, DIM / 256), 256>>>();

    // GEMM2: out = Hr@Cre^T + Hi@(-Cim)^T + X@D (5 register-accumulated passes)
    gemm_mma<<<dim3(DIM / 128, T_LEN / 128, 1), 256, 98304>>>(1, out);
}

// round 9
// speedup vs baseline: 1.4824x; 1.1579x over previous
#include <cuda_runtime.h>
#include <cuda_fp16.h>
#include <cstdint>

#define T_LEN 16384
#define DIM   1024
#define NCHUNK 256
#define CLEN   64

// ---------------- scratch (static device globals; no allocation) ----------------
__device__ __align__(16) float  g_gain[DIM];
__device__ float2 g_lam[DIM];
__device__ float2 g_lamL[DIM];
__device__ float2 g_carry [NCHUNK * DIM];
__device__ float2 g_carry2[NCHUNK * DIM];

// fp16 operands (all K-major: [row][k], k contiguous)
__device__ __align__(16) __half g_x16   [(size_t)T_LEN * DIM];   // X (fp16)
__device__ __align__(16) __half g_bure16[(size_t)T_LEN * DIM];   // Bu re
__device__ __align__(16) __half g_buim16[(size_t)T_LEN * DIM];   // Bu im
__device__ __align__(16) __half g_hre16 [(size_t)T_LEN * DIM];   // hidden re
__device__ __align__(16) __half g_him16 [(size_t)T_LEN * DIM];   // hidden im
__device__ __align__(16) __half g_brt16 [DIM * DIM];   // (B_re*gain)^T [h][i]
__device__ __align__(16) __half g_bit16 [DIM * DIM];   // (B_im*gain)^T [h][i]
__device__ __align__(16) __half g_cre16 [DIM * DIM];   // C_re          [o][h]
__device__ __align__(16) __half g_cin16 [DIM * DIM];   // -C_im         [o][h]
__device__ __align__(16) __half g_dt_hi [DIM * DIM];   // D^T hi        [o][i]
__device__ __align__(16) __half g_dt_lo [DIM * DIM];   // D^T lo        [o][i]

// ---------------- PTX helpers ----------------
__device__ __forceinline__ unsigned smem_u32(const void* p) {
    unsigned a;
    asm("{ .reg .u64 t; cvta.to.shared.u64 t, %1; cvt.u32.u64 %0, t; }" : "=r"(a) : "l"(p));
    return a;
}
__device__ __forceinline__ void ldsm4(uint32_t* r, unsigned a) {
    asm volatile("ldmatrix.sync.aligned.m8n8.x4.shared.b16 {%0,%1,%2,%3}, [%4];"
        : "=r"(r[0]), "=r"(r[1]), "=r"(r[2]), "=r"(r[3]) : "r"(a));
}
__device__ __forceinline__ void mma16816(float* c, const uint32_t* a, uint32_t b0, uint32_t b1) {
    asm volatile(
        "mma.sync.aligned.m16n8k16.row.col.f32.f16.f16.f32 "
        "{%0,%1,%2,%3}, {%4,%5,%6,%7}, {%8,%9}, {%0,%1,%2,%3};"
        : "+f"(c[0]), "+f"(c[1]), "+f"(c[2]), "+f"(c[3])
        : "r"(a[0]), "r"(a[1]), "r"(a[2]), "r"(a[3]), "r"(b0), "r"(b1));
}
__device__ __forceinline__ void cp16(unsigned dst, const void* src) {
    asm volatile("cp.async.cg.shared.global [%0], [%1], 16;" :: "r"(dst), "l"(src) : "memory");
}
#define CP_COMMIT() asm volatile("cp.async.commit_group;" ::: "memory")
#define CP_WAIT1()  asm volatile("cp.async.wait_group 1;" ::: "memory")

// ---------------- setup ----------------
__global__ void setup_kernel(const float* __restrict__ nu_log,
                             const float* __restrict__ theta_log,
                             const float* __restrict__ gamma_log) {
    int h = blockIdx.x * blockDim.x + threadIdx.x;
    if (h >= DIM) return;
    float nu = expf(nu_log[h]);
    float th = expf(theta_log[h]);
    float r  = expf(-nu);
    float lr = r * cosf(th);
    float li = r * sinf(th);
    g_lam[h] = make_float2(lr, li);
    float ar = lr, ai = li;
#pragma unroll
    for (int s = 0; s < 6; s++) {
        float nr = ar * ar - ai * ai;
        float ni = 2.0f * ar * ai;
        ar = nr; ai = ni;
    }
    g_lamL[h] = make_float2(ar, ai);
    g_gain[h] = expf(gamma_log[h]);
}

// ---------------- prep: elementwise fp16 convert ----------------
// mode 0: X, 1: Cre, 2: -Cim
__global__ __launch_bounds__(256) void conv_mat(const float* __restrict__ src, int mode, int n) {
    int i = (blockIdx.x * blockDim.x + threadIdx.x) * 4;
    if (i >= n) return;
    float4 v = *(const float4*)(src + i);
    float sign = (mode == 2) ? -1.0f : 1.0f;
    __half h4[4];
    h4[0] = __float2half_rn(v.x * sign);
    h4[1] = __float2half_rn(v.y * sign);
    h4[2] = __float2half_rn(v.z * sign);
    h4[3] = __float2half_rn(v.w * sign);
    __half* dst = (mode == 0) ? g_x16 : (mode == 1 ? g_cre16 : g_cin16);
    *(uint2*)(dst + i) = *(uint2*)h4;
}

// ---------------- prep: transpose + fp16 (gain-scaled B_re/B_im; D hi+lo split) ----------------
__global__ void transpose_conv(const float* __restrict__ src, int mode) {
    __shared__ float tl[32][33];
    int bx = blockIdx.x * 32, by = blockIdx.y * 32;
    int tx = threadIdx.x, ty = threadIdx.y;
    bool use_gain = (mode != 2);
#pragma unroll
    for (int r = 0; r < 4; r++) {
        int row = by + ty + r * 8;
        float v = src[(size_t)row * DIM + bx + tx];
        if (use_gain) v *= g_gain[row];
        tl[ty + r * 8][tx] = v;
    }
    __syncthreads();
    __half* hi = (mode == 0) ? g_brt16 : (mode == 1 ? g_bit16 : g_dt_hi);
#pragma unroll
    for (int r = 0; r < 4; r++) {
        float v = tl[tx][ty + r * 8];
        __half h = __float2half_rn(v);
        size_t o = (size_t)(bx + ty + r * 8) * DIM + by + tx;
        hi[o] = h;
        if (mode == 2) g_dt_lo[o] = __float2half_rn(v - __half2float(h));
    }
}

// ================= generic TN fp16 GEMM, BM=BN=128, BK=64, 3-stage ring =================
// smem: 3 x (A 16KB + B 16KB) = 96KB; regs capped for 2 CTAs/SM.

__device__ __forceinline__ void pass_ptrs(int mode, int z, int kt,
        const __half*& A, const __half*& B, int& k0) {
    if (mode == 0) {
        A = g_x16; B = z ? g_bit16 : g_brt16; k0 = kt * 64;
    } else {
        int p = kt >> 4; k0 = (kt & 15) * 64;
        switch (p) {
            case 0:  A = g_hre16; B = g_cre16; break;
            case 1:  A = g_him16; B = g_cin16; break;
            case 2:  A = g_x16;   B = g_dt_hi; break;
            default: A = g_x16;   B = g_dt_lo; break;
        }
    }
}

__global__ __launch_bounds__(256, 2) void gemm_mma(int mode, float* __restrict__ outp) {
    extern __shared__ __align__(128) char sm[];
    unsigned sbase = smem_u32(sm);
    const int tid = threadIdx.x, lane = tid & 31, w = tid >> 5;
    const int wm = w & 1, wn = w >> 1;
    const int n0 = blockIdx.x * 128, m0 = blockIdx.y * 128;
    const int z  = blockIdx.z;
    const int NK = (mode == 0) ? 16 : 64;

    float c[4][4][4];
#pragma unroll
    for (int a = 0; a < 4; a++)
#pragma unroll
        for (int b = 0; b < 4; b++)
#pragma unroll
            for (int d = 0; d < 4; d++) c[a][b][d] = 0.f;

    auto load_stage = [&](int stage, int kt) {
        const __half *A, *B; int k0;
        pass_ptrs(mode, z, kt, A, B, k0);
        unsigned sb = sbase + stage * 32768;
#pragma unroll
        for (int i = 0; i < 4; i++) {
            int idx = tid + i * 256; int row = idx >> 3, g = idx & 7;
            unsigned sw = (unsigned)(row * 128 + ((g ^ (row & 7)) << 4));
            cp16(sb + sw, A + (size_t)(m0 + row) * DIM + k0 + g * 8);
            cp16(sb + 16384 + sw, B + (size_t)(n0 + row) * DIM + k0 + g * 8);
        }
    };

    load_stage(0, 0); CP_COMMIT();
    load_stage(1, 1); CP_COMMIT();

    const int lr = lane & 15, lh = lane >> 4;
    int st = 0;                         // stage holding tile kt
    for (int kt = 0; kt < NK; kt++) {
        CP_WAIT1();
        __syncthreads();
        // issue next load into the free stage BEFORE compute
        if (kt + 2 < NK) {
            int free_st = st + 2; if (free_st >= 3) free_st -= 3;
            load_stage(free_st, kt + 2);
        }
        CP_COMMIT();
        unsigned sA = sbase + st * 32768;
        unsigned sB = sA + 16384;
#pragma unroll
        for (int ks = 0; ks < 4; ks++) {
            int kg = ks * 2 + lh;
            uint32_t bb[2][4];
#pragma unroll
            for (int nh = 0; nh < 2; nh++) {
                int row = wn * 32 + nh * 16 + lr;
                ldsm4(bb[nh], sB + row * 128 + ((kg ^ (row & 7)) << 4));
            }
            // one A fragment live at a time (register pressure: 2 CTAs/SM)
#pragma unroll
            for (int mf = 0; mf < 4; mf++) {
                uint32_t a[4];
                int row = wm * 64 + mf * 16 + lr;
                ldsm4(a, sA + row * 128 + ((kg ^ (row & 7)) << 4));
                mma16816(c[mf][0], a, bb[0][0], bb[0][2]);
                mma16816(c[mf][1], a, bb[0][1], bb[0][3]);
                mma16816(c[mf][2], a, bb[1][0], bb[1][2]);
                mma16816(c[mf][3], a, bb[1][1], bb[1][3]);
            }
        }
        st++; if (st >= 3) st = 0;
    }

    if (mode == 0) {
        __half* dst = z ? g_buim16 : g_bure16;
#pragma unroll
        for (int mf = 0; mf < 4; mf++) {
#pragma unroll
            for (int nf = 0; nf < 4; nf++) {
                int r   = wm * 64 + mf * 16 + (lane >> 2);
                int col = wn * 32 + nf * 8  + (lane & 3) * 2;
                size_t o = (size_t)(m0 + r) * DIM + n0 + col;
                *(__half2*)(dst + o) = __floats2half2_rn(c[mf][nf][0], c[mf][nf][1]);
                *(__half2*)(dst + o + 8 * DIM) = __floats2half2_rn(c[mf][nf][2], c[mf][nf][3]);
            }
        }
    } else {
#pragma unroll
        for (int mf = 0; mf < 4; mf++) {
#pragma unroll
            for (int nf = 0; nf < 4; nf++) {
                int r   = wm * 64 + mf * 16 + (lane >> 2);
                int col = wn * 32 + nf * 8  + (lane & 3) * 2;
                size_t o = (size_t)(m0 + r) * DIM + n0 + col;
                *(float2*)(outp + o) = make_float2(c[mf][nf][0], c[mf][nf][1]);
                *(float2*)(outp + o + 8 * DIM) = make_float2(c[mf][nf][2], c[mf][nf][3]);
            }
        }
    }
}

// ---------------- scan pass 1: chunk carries only (read-only on Bu) ----------------
__global__ __launch_bounds__(256) void scan_carry() {
    int h = blockIdx.y * blockDim.x + threadIdx.x;
    int c = blockIdx.x;
    float2 lam = g_lam[h];
    float ar = 0.f, ai = 0.f;
    size_t idx = (size_t)c * CLEN * DIM + h;
#pragma unroll 4
    for (int t = 0; t < CLEN; t++, idx += DIM) {
        float br = __half2float(g_bure16[idx]);
        float bi = __half2float(g_buim16[idx]);
        float nr = fmaf(lam.x, ar, fmaf(-lam.y, ai, br));
        float ni = fmaf(lam.x, ai, fmaf( lam.y, ar, bi));
        ar = nr; ai = ni;
    }
    g_carry[c * DIM + h] = make_float2(ar, ai);
}

// ---------------- scan pass 2: prefix over chunk carries (batched loads for MLP) ----------------
__global__ __launch_bounds__(256) void scan_chunks() {
    int h = blockIdx.x * blockDim.x + threadIdx.x;
    float2 lamL = g_lamL[h];
    float pr = 0.f, pi = 0.f;
    for (int cb = 0; cb < NCHUNK; cb += 32) {
        float2 e[32];
#pragma unroll
        for (int j = 0; j < 32; j++) e[j] = g_carry[(cb + j) * DIM + h];
#pragma unroll
        for (int j = 0; j < 32; j++) {
            float nr = fmaf(lamL.x, pr, fmaf(-lamL.y, pi, e[j].x));
            float ni = fmaf(lamL.x, pi, fmaf( lamL.y, pr, e[j].y));
            pr = nr; pi = ni;
            e[j] = make_float2(pr, pi);
        }
#pragma unroll
        for (int j = 0; j < 32; j++) g_carry2[(cb + j) * DIM + h] = e[j];
    }
}

// ---------------- scan pass 3: rerun recurrence with carry-in, write fp16 H ----------------
__global__ __launch_bounds__(256) void scan_apply_all() {
    int h = blockIdx.y * blockDim.x + threadIdx.x;
    int c = blockIdx.x;
    float2 P = (c == 0) ? make_float2(0.f, 0.f) : g_carry2[(c - 1) * DIM + h];
    float2 lam = g_lam[h];
    float ar = P.x, ai = P.y;
    size_t idx = (size_t)c * CLEN * DIM + h;
#pragma unroll 4
    for (int t = 0; t < CLEN; t++, idx += DIM) {
        float br = __half2float(g_bure16[idx]);
        float bi = __half2float(g_buim16[idx]);
        float nr = fmaf(lam.x, ar, fmaf(-lam.y, ai, br));
        float ni = fmaf(lam.x, ai, fmaf( lam.y, ar, bi));
        ar = nr; ai = ni;
        g_hre16[idx] = __float2half_rn(ar);
        g_him16[idx] = __float2half_rn(ai);
    }
}

// ---------------- launch ----------------
extern "C" void kernel_launch(void* const* d_in, const int* in_sizes, int n_in,
                              void* d_out, int out_size) {
    const float* X         = (const float*)d_in[0];
    const float* nu_log    = (const float*)d_in[1];
    const float* theta_log = (const float*)d_in[2];
    const float* gamma_log = (const float*)d_in[3];
    const float* Bre       = (const float*)d_in[4];
    const float* Bim       = (const float*)d_in[5];
    const float* Cre       = (const float*)d_in[6];
    const float* Cim       = (const float*)d_in[7];
    const float* Dm        = (const float*)d_in[8];
    float* out             = (float*)d_out;

    cudaFuncSetAttribute(gemm_mma, cudaFuncAttributeMaxDynamicSharedMemorySize, 98304);

    setup_kernel<<<4, 256>>>(nu_log, theta_log, gamma_log);
    conv_mat<<<T_LEN * DIM / 4 / 256, 256>>>(X, 0, T_LEN * DIM);
    conv_mat<<<DIM * DIM / 4 / 256, 256>>>(Cre, 1, DIM * DIM);
    conv_mat<<<DIM * DIM / 4 / 256, 256>>>(Cim, 2, DIM * DIM);
    transpose_conv<<<dim3(32, 32), dim3(32, 8)>>>(Bre, 0);
    transpose_conv<<<dim3(32, 32), dim3(32, 8)>>>(Bim, 1);
    transpose_conv<<<dim3(32, 32), dim3(32, 8)>>>(Dm, 2);

    // GEMM1: Bu_re / Bu_im via blockIdx.z, fp16 output
    gemm_mma<<<dim3(DIM / 128, T_LEN / 128, 2), 256, 98304>>>(0, nullptr);

    scan_carry<<<dim3(NCHUNK, DIM / 256), 256>>>();
    scan_chunks<<<DIM / 256, 256>>>();
    scan_apply_all<<<dim3(NCHUNK, DIM / 256), 256>>>();

    // GEMM2: out = Hr@Cre^T + Hi@(-Cim)^T + X@(D_hi+D_lo)  (4 passes, 64 k-tiles)
    gemm_mma<<<dim3(DIM / 128, T_LEN / 128, 1), 256, 98304>>>(1, out);
}

// round 10
// speedup vs baseline: 1.7097x; 1.1534x over previous
#include <cuda_runtime.h>
#include <cuda_fp16.h>
#include <cstdint>

#define T_LEN 16384
#define DIM   1024
#define NCHUNK 256
#define CLEN   64

// ---------------- scratch (static device globals; no allocation) ----------------
__device__ __align__(16) float  g_gain[DIM];
__device__ float2 g_lam[DIM];
__device__ float2 g_lamL[DIM];
__device__ float2 g_carry [NCHUNK * DIM];
__device__ float2 g_carry2[NCHUNK * DIM];

// fp16 operands (all K-major: [row][k], k contiguous)
__device__ __align__(16) __half g_x16   [(size_t)T_LEN * DIM];   // X (fp16)
__device__ __align__(16) __half g_bure16[(size_t)T_LEN * DIM];   // Bu re
__device__ __align__(16) __half g_buim16[(size_t)T_LEN * DIM];   // Bu im
__device__ __align__(16) __half g_hre16 [(size_t)T_LEN * DIM];   // hidden re
__device__ __align__(16) __half g_him16 [(size_t)T_LEN * DIM];   // hidden im
__device__ __align__(16) __half g_brt16 [DIM * DIM];   // (B_re*gain)^T [h][i]
__device__ __align__(16) __half g_bit16 [DIM * DIM];   // (B_im*gain)^T [h][i]
__device__ __align__(16) __half g_cre16 [DIM * DIM];   // C_re          [o][h]
__device__ __align__(16) __half g_cin16 [DIM * DIM];   // -C_im         [o][h]
__device__ __align__(16) __half g_dt16  [DIM * DIM];   // D^T           [o][i]

// ---------------- PTX helpers ----------------
__device__ __forceinline__ unsigned smem_u32(const void* p) {
    unsigned a;
    asm("{ .reg .u64 t; cvta.to.shared.u64 t, %1; cvt.u32.u64 %0, t; }" : "=r"(a) : "l"(p));
    return a;
}
__device__ __forceinline__ void ldsm4(uint32_t* r, unsigned a) {
    asm volatile("ldmatrix.sync.aligned.m8n8.x4.shared.b16 {%0,%1,%2,%3}, [%4];"
        : "=r"(r[0]), "=r"(r[1]), "=r"(r[2]), "=r"(r[3]) : "r"(a));
}
__device__ __forceinline__ void mma16816(float* c, const uint32_t* a, uint32_t b0, uint32_t b1) {
    asm volatile(
        "mma.sync.aligned.m16n8k16.row.col.f32.f16.f16.f32 "
        "{%0,%1,%2,%3}, {%4,%5,%6,%7}, {%8,%9}, {%0,%1,%2,%3};"
        : "+f"(c[0]), "+f"(c[1]), "+f"(c[2]), "+f"(c[3])
        : "r"(a[0]), "r"(a[1]), "r"(a[2]), "r"(a[3]), "r"(b0), "r"(b1));
}
__device__ __forceinline__ void cp16(unsigned dst, const void* src) {
    asm volatile("cp.async.cg.shared.global [%0], [%1], 16;" :: "r"(dst), "l"(src) : "memory");
}
#define CP_COMMIT() asm volatile("cp.async.commit_group;" ::: "memory")
#define CP_WAIT1()  asm volatile("cp.async.wait_group 1;" ::: "memory")

// ---------------- setup ----------------
__global__ void setup_kernel(const float* __restrict__ nu_log,
                             const float* __restrict__ theta_log,
                             const float* __restrict__ gamma_log) {
    int h = blockIdx.x * blockDim.x + threadIdx.x;
    if (h >= DIM) return;
    float nu = expf(nu_log[h]);
    float th = expf(theta_log[h]);
    float r  = expf(-nu);
    float lr = r * cosf(th);
    float li = r * sinf(th);
    g_lam[h] = make_float2(lr, li);
    float ar = lr, ai = li;
#pragma unroll
    for (int s = 0; s < 6; s++) {
        float nr = ar * ar - ai * ai;
        float ni = 2.0f * ar * ai;
        ar = nr; ai = ni;
    }
    g_lamL[h] = make_float2(ar, ai);
    g_gain[h] = expf(gamma_log[h]);
}

// ---------------- prep: elementwise fp16 convert ----------------
// mode 0: X, 1: Cre, 2: -Cim
__global__ __launch_bounds__(256) void conv_mat(const float* __restrict__ src, int mode, int n) {
    int i = (blockIdx.x * blockDim.x + threadIdx.x) * 4;
    if (i >= n) return;
    float4 v = *(const float4*)(src + i);
    float sign = (mode == 2) ? -1.0f : 1.0f;
    __half h4[4];
    h4[0] = __float2half_rn(v.x * sign);
    h4[1] = __float2half_rn(v.y * sign);
    h4[2] = __float2half_rn(v.z * sign);
    h4[3] = __float2half_rn(v.w * sign);
    __half* dst = (mode == 0) ? g_x16 : (mode == 1 ? g_cre16 : g_cin16);
    *(uint2*)(dst + i) = *(uint2*)h4;
}

// ---------------- prep: transpose + fp16 (gain-scaled B_re/B_im; D) ----------------
__global__ void transpose_conv(const float* __restrict__ src, int mode) {
    __shared__ float tl[32][33];
    int bx = blockIdx.x * 32, by = blockIdx.y * 32;
    int tx = threadIdx.x, ty = threadIdx.y;
    bool use_gain = (mode != 2);
#pragma unroll
    for (int r = 0; r < 4; r++) {
        int row = by + ty + r * 8;
        float v = src[(size_t)row * DIM + bx + tx];
        if (use_gain) v *= g_gain[row];
        tl[ty + r * 8][tx] = v;
    }
    __syncthreads();
    __half* dst = (mode == 0) ? g_brt16 : (mode == 1 ? g_bit16 : g_dt16);
#pragma unroll
    for (int r = 0; r < 4; r++) {
        float v = tl[tx][ty + r * 8];
        size_t o = (size_t)(bx + ty + r * 8) * DIM + by + tx;
        dst[o] = __float2half_rn(v);
    }
}

// ================= generic TN fp16 GEMM, BM=BN=128, BK=64, 3-stage ring =================
// smem: 3 x (A 16KB + B 16KB) = 96KB; regs capped for 2 CTAs/SM.

__device__ __forceinline__ void pass_ptrs(int mode, int z, int kt,
        const __half*& A, const __half*& B, int& k0) {
    if (mode == 0) {
        A = g_x16; B = z ? g_bit16 : g_brt16; k0 = kt * 64;
    } else {
        int p = kt >> 4; k0 = (kt & 15) * 64;
        switch (p) {
            case 0:  A = g_hre16; B = g_cre16; break;
            case 1:  A = g_him16; B = g_cin16; break;
            default: A = g_x16;   B = g_dt16;  break;
        }
    }
}

__global__ __launch_bounds__(256, 2) void gemm_mma(int mode, float* __restrict__ outp) {
    extern __shared__ __align__(128) char sm[];
    unsigned sbase = smem_u32(sm);
    const int tid = threadIdx.x, lane = tid & 31, w = tid >> 5;
    const int wm = w & 1, wn = w >> 1;
    const int n0 = blockIdx.x * 128, m0 = blockIdx.y * 128;
    const int z  = blockIdx.z;
    const int NK = (mode == 0) ? 16 : 48;

    float c[4][4][4];
#pragma unroll
    for (int a = 0; a < 4; a++)
#pragma unroll
        for (int b = 0; b < 4; b++)
#pragma unroll
            for (int d = 0; d < 4; d++) c[a][b][d] = 0.f;

    auto load_stage = [&](int stage, int kt) {
        const __half *A, *B; int k0;
        pass_ptrs(mode, z, kt, A, B, k0);
        unsigned sb = sbase + stage * 32768;
#pragma unroll
        for (int i = 0; i < 4; i++) {
            int idx = tid + i * 256; int row = idx >> 3, g = idx & 7;
            unsigned sw = (unsigned)(row * 128 + ((g ^ (row & 7)) << 4));
            cp16(sb + sw, A + (size_t)(m0 + row) * DIM + k0 + g * 8);
            cp16(sb + 16384 + sw, B + (size_t)(n0 + row) * DIM + k0 + g * 8);
        }
    };

    load_stage(0, 0); CP_COMMIT();
    load_stage(1, 1); CP_COMMIT();

    const int lr = lane & 15, lh = lane >> 4;
    int st = 0;                         // stage holding tile kt
    for (int kt = 0; kt < NK; kt++) {
        CP_WAIT1();
        __syncthreads();
        // issue next load into the free stage BEFORE compute
        if (kt + 2 < NK) {
            int free_st = st + 2; if (free_st >= 3) free_st -= 3;
            load_stage(free_st, kt + 2);
        }
        CP_COMMIT();
        unsigned sA = sbase + st * 32768;
        unsigned sB = sA + 16384;
#pragma unroll
        for (int ks = 0; ks < 4; ks++) {
            int kg = ks * 2 + lh;
            uint32_t bb[2][4];
#pragma unroll
            for (int nh = 0; nh < 2; nh++) {
                int row = wn * 32 + nh * 16 + lr;
                ldsm4(bb[nh], sB + row * 128 + ((kg ^ (row & 7)) << 4));
            }
            // one A fragment live at a time (register pressure: 2 CTAs/SM)
#pragma unroll
            for (int mf = 0; mf < 4; mf++) {
                uint32_t a[4];
                int row = wm * 64 + mf * 16 + lr;
                ldsm4(a, sA + row * 128 + ((kg ^ (row & 7)) << 4));
                mma16816(c[mf][0], a, bb[0][0], bb[0][2]);
                mma16816(c[mf][1], a, bb[0][1], bb[0][3]);
                mma16816(c[mf][2], a, bb[1][0], bb[1][2]);
                mma16816(c[mf][3], a, bb[1][1], bb[1][3]);
            }
        }
        st++; if (st >= 3) st = 0;
    }

    if (mode == 0) {
        __half* dst = z ? g_buim16 : g_bure16;
#pragma unroll
        for (int mf = 0; mf < 4; mf++) {
#pragma unroll
            for (int nf = 0; nf < 4; nf++) {
                int r   = wm * 64 + mf * 16 + (lane >> 2);
                int col = wn * 32 + nf * 8  + (lane & 3) * 2;
                size_t o = (size_t)(m0 + r) * DIM + n0 + col;
                *(__half2*)(dst + o) = __floats2half2_rn(c[mf][nf][0], c[mf][nf][1]);
                *(__half2*)(dst + o + 8 * DIM) = __floats2half2_rn(c[mf][nf][2], c[mf][nf][3]);
            }
        }
    } else {
#pragma unroll
        for (int mf = 0; mf < 4; mf++) {
#pragma unroll
            for (int nf = 0; nf < 4; nf++) {
                int r   = wm * 64 + mf * 16 + (lane >> 2);
                int col = wn * 32 + nf * 8  + (lane & 3) * 2;
                size_t o = (size_t)(m0 + r) * DIM + n0 + col;
                *(float2*)(outp + o) = make_float2(c[mf][nf][0], c[mf][nf][1]);
                *(float2*)(outp + o + 8 * DIM) = make_float2(c[mf][nf][2], c[mf][nf][3]);
            }
        }
    }
}

// ---------------- scan pass 1: chunk carries only (read-only on Bu) ----------------
__global__ __launch_bounds__(256) void scan_carry() {
    int h = blockIdx.y * blockDim.x + threadIdx.x;
    int c = blockIdx.x;
    float2 lam = g_lam[h];
    float ar = 0.f, ai = 0.f;
    size_t idx = (size_t)c * CLEN * DIM + h;
#pragma unroll 4
    for (int t = 0; t < CLEN; t++, idx += DIM) {
        float br = __half2float(g_bure16[idx]);
        float bi = __half2float(g_buim16[idx]);
        float nr = fmaf(lam.x, ar, fmaf(-lam.y, ai, br));
        float ni = fmaf(lam.x, ai, fmaf( lam.y, ar, bi));
        ar = nr; ai = ni;
    }
    g_carry[c * DIM + h] = make_float2(ar, ai);
}

// ---------------- scan pass 2: prefix over chunk carries (batched loads for MLP) ----------------
__global__ __launch_bounds__(256) void scan_chunks() {
    int h = blockIdx.x * blockDim.x + threadIdx.x;
    float2 lamL = g_lamL[h];
    float pr = 0.f, pi = 0.f;
    for (int cb = 0; cb < NCHUNK; cb += 32) {
        float2 e[32];
#pragma unroll
        for (int j = 0; j < 32; j++) e[j] = g_carry[(cb + j) * DIM + h];
#pragma unroll
        for (int j = 0; j < 32; j++) {
            float nr = fmaf(lamL.x, pr, fmaf(-lamL.y, pi, e[j].x));
            float ni = fmaf(lamL.x, pi, fmaf( lamL.y, pr, e[j].y));
            pr = nr; pi = ni;
            e[j] = make_float2(pr, pi);
        }
#pragma unroll
        for (int j = 0; j < 32; j++) g_carry2[(cb + j) * DIM + h] = e[j];
    }
}

// ---------------- scan pass 3: rerun recurrence with carry-in, write fp16 H ----------------
__global__ __launch_bounds__(256) void scan_apply_all() {
    int h = blockIdx.y * blockDim.x + threadIdx.x;
    int c = blockIdx.x;
    float2 P = (c == 0) ? make_float2(0.f, 0.f) : g_carry2[(c - 1) * DIM + h];
    float2 lam = g_lam[h];
    float ar = P.x, ai = P.y;
    size_t idx = (size_t)c * CLEN * DIM + h;
#pragma unroll 4
    for (int t = 0; t < CLEN; t++, idx += DIM) {
        float br = __half2float(g_bure16[idx]);
        float bi = __half2float(g_buim16[idx]);
        float nr = fmaf(lam.x, ar, fmaf(-lam.y, ai, br));
        float ni = fmaf(lam.x, ai, fmaf( lam.y, ar, bi));
        ar = nr; ai = ni;
        g_hre16[idx] = __float2half_rn(ar);
        g_him16[idx] = __float2half_rn(ai);
    }
}

// ---------------- launch ----------------
extern "C" void kernel_launch(void* const* d_in, const int* in_sizes, int n_in,
                              void* d_out, int out_size) {
    const float* X         = (const float*)d_in[0];
    const float* nu_log    = (const float*)d_in[1];
    const float* theta_log = (const float*)d_in[2];
    const float* gamma_log = (const float*)d_in[3];
    const float* Bre       = (const float*)d_in[4];
    const float* Bim       = (const float*)d_in[5];
    const float* Cre       = (const float*)d_in[6];
    const float* Cim       = (const float*)d_in[7];
    const float* Dm        = (const float*)d_in[8];
    float* out             = (float*)d_out;

    cudaFuncSetAttribute(gemm_mma, cudaFuncAttributeMaxDynamicSharedMemorySize, 98304);

    setup_kernel<<<4, 256>>>(nu_log, theta_log, gamma_log);
    conv_mat<<<T_LEN * DIM / 4 / 256, 256>>>(X, 0, T_LEN * DIM);
    conv_mat<<<DIM * DIM / 4 / 256, 256>>>(Cre, 1, DIM * DIM);
    conv_mat<<<DIM * DIM / 4 / 256, 256>>>(Cim, 2, DIM * DIM);
    transpose_conv<<<dim3(32, 32), dim3(32, 8)>>>(Bre, 0);
    transpose_conv<<<dim3(32, 32), dim3(32, 8)>>>(Bim, 1);
    transpose_conv<<<dim3(32, 32), dim3(32, 8)>>>(Dm, 2);

    // GEMM1: Bu_re / Bu_im via blockIdx.z, fp16 output
    gemm_mma<<<dim3(DIM / 128, T_LEN / 128, 2), 256, 98304>>>(0, nullptr);

    scan_carry<<<dim3(NCHUNK, DIM / 256), 256>>>();
    scan_chunks<<<DIM / 256, 256>>>();
    scan_apply_all<<<dim3(NCHUNK, DIM / 256), 256>>>();

    // GEMM2: out = Hr@Cre^T + Hi@(-Cim)^T + X@D  (3 passes, 48 k-tiles)
    gemm_mma<<<dim3(DIM / 128, T_LEN / 128, 1), 256, 98304>>>(1, out);
}